// round 5
// baseline (speedup 1.0000x reference)
#include <cuda_runtime.h>
#include <math.h>
#include <stdint.h>

// ----------------------------------------------------------------------------
// BidirectionalPropagation (BasicVSR++ style) on GB300. B=1,T=8,C=64,96x96,DG=16
// R4: FFMA2 (fma.rn.f32x2) in conv3x3 + gemm; duplicated-weight smem staging
//     so packed weight operands come straight from LDS (no packing cost).
// ----------------------------------------------------------------------------

#define HWP 9216          // 96*96
#define CH  (64 * HWP)

__device__ float g_fb[8][CH];
__device__ float g_ff[8][CH];
__device__ float g_hA[CH];
__device__ float g_hB[CH];
__device__ float g_out4[432 * HWP];
__device__ float g_cols[1152 * HWP];
__device__ float g_dcn[CH];

// conv smem stage: input 8 cins x 18 rows x 40 cols + dup weights 8 x 9 x 4 x 2
#define ROWW   40
#define CINSZ  (18 * ROWW)          // 720 floats per cin
#define SW_OFF (8 * CINSZ)          // 5760
#define STG_F  (SW_OFF + 576)       // 6336 floats per stage
#define NSTG   3
#define CONV_SMEM (NSTG * STG_F * 4)  // 76032 bytes

typedef unsigned long long u64;

__device__ __forceinline__ u64 ffma2(u64 a, u64 b, u64 c) {
    u64 d;
    asm("fma.rn.f32x2 %0, %1, %2, %3;" : "=l"(d) : "l"(a), "l"(b), "l"(c));
    return d;
}
__device__ __forceinline__ u64 pk(float lo, float hi) {
    u64 d;
    asm("mov.b64 %0, {%1, %2};" : "=l"(d) : "f"(lo), "f"(hi));
    return d;
}
__device__ __forceinline__ void upk(u64 v, float& lo, float& hi) {
    asm("mov.b64 {%0, %1}, %2;" : "=f"(lo), "=f"(hi) : "l"(v));
}

__device__ __forceinline__ void cp16(uint32_t d, const void* g, int sz) {
    asm volatile("cp.async.ca.shared.global [%0], [%1], 16, %2;\n"
                 :: "r"(d), "l"(g), "r"(sz));
}
__device__ __forceinline__ void cp4(uint32_t d, const void* g) {
    asm volatile("cp.async.ca.shared.global [%0], [%1], 4;\n"
                 :: "r"(d), "l"(g));
}
#define CP_COMMIT() asm volatile("cp.async.commit_group;\n" ::: "memory")
#define CP_WAIT1()  asm volatile("cp.async.wait_group 1;\n" ::: "memory")

// ---------------------------------------------------------------------------
// conv3x3: tile 32x16 px, 128 threads, thread = 4 consecutive px x 4 couts.
// grid = (18, Cout/4). Up to three 64-ch input blocks (nullptr => zeros).
// Accumulators are f32x2 pairs over pixel pairs (j0,j1) / (j2,j3).
// ---------------------------------------------------------------------------
__global__ __launch_bounds__(128) void conv3x3_k(
    const float* __restrict__ in0, const float* __restrict__ in1,
    const float* __restrict__ in2, int cinBlocks,
    const float* __restrict__ wgt, const float* __restrict__ bias,
    const float* __restrict__ addsrc, float* __restrict__ out, int act)
{
    extern __shared__ float smem[];
    const int tid = threadIdx.x;
    const int tX = (blockIdx.x % 3) * 32;
    const int tY = (blockIdx.x / 3) * 16;
    const int coBase = blockIdx.y * 4;
    const int txg = tid & 7;
    const int ty  = tid >> 3;
    const int Cin = cinBlocks * 64;

    const float* ptrs[3] = {in0, in1, in2};
    const float* actp[3]; int actc[3]; int na = 0;
    for (int b = 0; b < cinBlocks; b++)
        if (ptrs[b]) { actp[na] = ptrs[b]; actc[na] = b * 64; na++; }
    const int nSuper = na * 8;

    // ---- precompute staging tuples ----
    // input: 1440 float4 slots; slot = c*180 + r*10 + q
    int in_goff[12]; unsigned in_val = 0;
#pragma unroll
    for (int i = 0; i < 12; i++) {
        int slot = tid + i * 128;
        int c = slot / 180; int rem = slot - c * 180;
        int r = rem / 10;   int q = rem - r * 10;
        int gy = tY - 1 + r, gx = tX - 4 + q * 4;
        bool v = ((unsigned)gy < 96u) && ((unsigned)gx < 96u);
        in_goff[i] = v ? (c * HWP + gy * 96 + gx) : 0;
        if (v) in_val |= (1u << i);
    }
    // weights (duplicated): 576 scalar slots; slot = c*72 + k9*8 + co*2 + d
    int w_goff[5];
#pragma unroll
    for (int i = 0; i < 5; i++) {
        int slot = tid + i * 128;
        if (slot < 576) {
            int c = slot / 72; int rem = slot - c * 72;
            int k9 = rem >> 3; int co = (rem & 7) >> 1;
            w_goff[i] = ((coBase + co) * Cin + c) * 9 + k9;
        } else w_goff[i] = 0;
    }

    const uint32_t s32 = (uint32_t)__cvta_generic_to_shared(smem);

    auto PREFETCH = [&](int sb, int stg) {
        const float* base = actp[sb >> 3] + ((sb & 7) * 8) * HWP;
        const uint32_t d0 = s32 + (uint32_t)stg * (STG_F * 4) + tid * 16;
#pragma unroll
        for (int i = 0; i < 11; i++)
            cp16(d0 + i * 2048, base + in_goff[i], ((in_val >> i) & 1) ? 16 : 0);
        if (tid < 32)
            cp16(d0 + 11 * 2048, base + in_goff[11], ((in_val >> 11) & 1) ? 16 : 0);
        const float* wbase = wgt + (actc[sb >> 3] + (sb & 7) * 8) * 9;
        const uint32_t w0 = s32 + (uint32_t)stg * (STG_F * 4) + SW_OFF * 4 + tid * 4;
        cp4(w0,        wbase + w_goff[0]);
        cp4(w0 + 512,  wbase + w_goff[1]);
        cp4(w0 + 1024, wbase + w_goff[2]);
        cp4(w0 + 1536, wbase + w_goff[3]);
        if (tid < 64) cp4(w0 + 2048, wbase + w_goff[4]);
    };

    u64 acc2[8];   // [co*2 + jp] : (px jp*2, px jp*2+1)
#pragma unroll
    for (int i = 0; i < 8; i++) acc2[i] = pk(0.f, 0.f);

    PREFETCH(0, 0); CP_COMMIT();
    PREFETCH(1, 1); CP_COMMIT();

    int stg = 0, pstg = 2;
    for (int s = 0; s < nSuper; s++) {
        CP_WAIT1();
        __syncthreads();
        const float* st = smem + stg * STG_F;

#pragma unroll
        for (int c = 0; c < 8; c++) {
            const float* sp = st + c * CINSZ + ty * ROWW + txg * 4;
            // load 6 input values per row, build 5 packed pairs per row
            u64 pr[3][5];
#pragma unroll
            for (int r = 0; r < 3; r++) {
                const float4 m = *(const float4*)(sp + r * ROWW + 4);
                const float e0 = sp[r * ROWW + 3];
                const float e5 = sp[r * ROWW + 8];
                pr[r][0] = pk(e0,  m.x);
                pr[r][1] = pk(m.x, m.y);
                pr[r][2] = pk(m.y, m.z);
                pr[r][3] = pk(m.z, m.w);
                pr[r][4] = pk(m.w, e5);
            }
            const ulonglong2* wp2 = (const ulonglong2*)(st + SW_OFF + c * 72);
#pragma unroll
            for (int k9 = 0; k9 < 9; k9++) {
                const ulonglong2 wA = wp2[k9 * 2];       // (w0,w0) (w1,w1)
                const ulonglong2 wB = wp2[k9 * 2 + 1];   // (w2,w2) (w3,w3)
                const int r = k9 / 3, cc = k9 - r * 3;
                const u64 p0 = pr[r][cc];
                const u64 p1 = pr[r][cc + 2];
                acc2[0] = ffma2(p0, wA.x, acc2[0]);
                acc2[1] = ffma2(p1, wA.x, acc2[1]);
                acc2[2] = ffma2(p0, wA.y, acc2[2]);
                acc2[3] = ffma2(p1, wA.y, acc2[3]);
                acc2[4] = ffma2(p0, wB.x, acc2[4]);
                acc2[5] = ffma2(p1, wB.x, acc2[5]);
                acc2[6] = ffma2(p0, wB.y, acc2[6]);
                acc2[7] = ffma2(p1, wB.y, acc2[7]);
            }
        }

        if (s + 2 < nSuper) PREFETCH(s + 2, pstg);
        CP_COMMIT();
        stg = (stg == 2) ? 0 : stg + 1;
        pstg = (pstg == 2) ? 0 : pstg + 1;
    }

    const int y = tY + ty;
    const int xb = tX + txg * 4;
    const int px = y * 96 + xb;
#pragma unroll
    for (int co = 0; co < 4; co++) {
        const float b = bias[coBase + co];
        float4 v;
        upk(acc2[co * 2 + 0], v.x, v.y);
        upk(acc2[co * 2 + 1], v.z, v.w);
        v.x += b; v.y += b; v.z += b; v.w += b;
        if (act) {
            v.x = (v.x >= 0.f) ? v.x : 0.1f * v.x;
            v.y = (v.y >= 0.f) ? v.y : 0.1f * v.y;
            v.z = (v.z >= 0.f) ? v.z : 0.1f * v.z;
            v.w = (v.w >= 0.f) ? v.w : 0.1f * v.w;
        }
        const int o = (coBase + co) * HWP + px;
        if (addsrc) {
            float4 a = *(const float4*)(addsrc + o);
            v.x += a.x; v.y += a.y; v.z += a.z; v.w += a.w;
        }
        *(float4*)(out + o) = v;
    }
}

// ---------------------------------------------------------------------------
// Modulated deformable sampling. grid = (72, 144) = (pix/128, dg*K).
// ---------------------------------------------------------------------------
__global__ __launch_bounds__(128) void dcn_sample_k(
    const float* __restrict__ xin0, const float* __restrict__ xin1,
    const float* __restrict__ out4, float* __restrict__ cols)
{
    const int pix = blockIdx.x * 128 + threadIdx.x;
    const int gk = blockIdx.y;
    const int g = gk / 9, k = gk - g * 9;
    const int h = pix / 96, w = pix - h * 96;

    const float offY = 5.f * tanhf(out4[(gk * 2 + 0) * HWP + pix]);
    const float offX = 5.f * tanhf(out4[(gk * 2 + 1) * HWP + pix]);
    const float mraw = out4[(288 + gk) * HWP + pix];
    const float m = 1.f / (1.f + expf(-mraw));

    const int ky = k / 3, kx = k - ky * 3;
    const float sy = offY + (float)(h - 1 + ky);
    const float sx = offX + (float)(w - 1 + kx);
    const float y0f = floorf(sy), x0f = floorf(sx);
    const float fy = sy - y0f, fx = sx - x0f;
    const int y0 = (int)y0f, x0 = (int)x0f;

    const bool vy0 = (y0 >= 0) && (y0 < 96);
    const bool vy1 = (y0 + 1 >= 0) && (y0 + 1 < 96);
    const bool vx0 = (x0 >= 0) && (x0 < 96);
    const bool vx1 = (x0 + 1 >= 0) && (x0 + 1 < 96);
    const int cy0 = min(max(y0, 0), 95), cy1 = min(max(y0 + 1, 0), 95);
    const int cx0 = min(max(x0, 0), 95), cx1 = min(max(x0 + 1, 0), 95);

    const float w00 = (1.f - fy) * (1.f - fx) * ((vy0 && vx0) ? 1.f : 0.f);
    const float w01 = (1.f - fy) * fx         * ((vy0 && vx1) ? 1.f : 0.f);
    const float w10 = fy * (1.f - fx)         * ((vy1 && vx0) ? 1.f : 0.f);
    const float w11 = fy * fx                 * ((vy1 && vx1) ? 1.f : 0.f);

    const int i00 = cy0 * 96 + cx0, i01 = cy0 * 96 + cx1;
    const int i10 = cy1 * 96 + cx0, i11 = cy1 * 96 + cx1;

#pragma unroll
    for (int c = 0; c < 8; c++) {
        const int cin = g * 8 + c;
        const float* p = (cin < 64) ? xin0 : xin1;
        float v = 0.f;
        if (p) {
            const float* pc = p + (cin & 63) * HWP;
            v = w00 * pc[i00] + w01 * pc[i01] + w10 * pc[i10] + w11 * pc[i11];
        }
        cols[(cin * 9 + k) * HWP + pix] = v * m;
    }
}

// ---------------------------------------------------------------------------
// GEMM: out[64,HWP] = W[64,K] @ in[K,HWP] + bias (+add). grid = (36, 8).
// FFMA2 over the natural (px0,px1) pair; weights duplicated in smem.
// ---------------------------------------------------------------------------
__global__ __launch_bounds__(128) void gemm_k(
    const float* __restrict__ in0, const float* __restrict__ in1,
    int ksplit, int K,
    const float* __restrict__ wgt, const float* __restrict__ bias,
    const float* __restrict__ addsrc, float* __restrict__ out)
{
    __shared__ float s_w[8][16];   // [kk][co*2 + d], duplicated weights
    const int tid = threadIdx.x;
    const int pix0 = blockIdx.x * 256 + tid * 2;
    const int coBase = blockIdx.y * 8;

    u64 acc2[8];
#pragma unroll
    for (int i = 0; i < 8; i++) acc2[i] = pk(0.f, 0.f);

    for (int k0 = 0; k0 < K; k0 += 8) {
        __syncthreads();
        {
            // 128 slots: kk = tid>>4, co = (tid&15)>>1 (each weight written twice)
            int kk = tid >> 4, co = (tid & 15) >> 1;
            s_w[kk][tid & 15] = wgt[(coBase + co) * K + k0 + kk];
        }
        __syncthreads();
#pragma unroll
        for (int kk = 0; kk < 8; kk++) {
            const int k = k0 + kk;
            const float* p = (k < ksplit) ? (in0 + k * HWP)
                                          : (in1 + (k - ksplit) * HWP);
            const float2 v = *(const float2*)(p + pix0);
            const u64 vv = pk(v.x, v.y);
            const u64* wp = (const u64*)&s_w[kk][0];
#pragma unroll
            for (int co = 0; co < 8; co++)
                acc2[co] = ffma2(vv, wp[co], acc2[co]);
        }
    }

#pragma unroll
    for (int co = 0; co < 8; co++) {
        const float b = bias[coBase + co];
        float2 v; upk(acc2[co], v.x, v.y);
        v.x += b; v.y += b;
        const int o = (coBase + co) * HWP + pix0;
        if (addsrc) {
            float2 a = *(const float2*)(addsrc + o);
            v.x += a.x; v.y += a.y;
        }
        *(float2*)(out + o) = v;
    }
}

// ---------------------------------------------------------------------------
// Host orchestration
// ---------------------------------------------------------------------------
extern "C" void kernel_launch(void* const* d_in, const int* in_sizes, int n_in,
                              void* d_out, int out_size)
{
    (void)in_sizes; (void)n_in; (void)out_size;

    cudaFuncSetAttribute(conv3x3_k, cudaFuncAttributeMaxDynamicSharedMemorySize,
                         CONV_SMEM);

    const float* x = (const float*)d_in[0];
    const float* P[2][14];
    for (int j = 0; j < 14; j++) {
        P[0][j] = (const float*)d_in[1 + j];
        P[1][j] = (const float*)d_in[15 + j];
    }
    const float* fus_w = (const float*)d_in[29];
    const float* fus_b = (const float*)d_in[30];
    float* out = (float*)d_out;

    float *fb, *ff, *hA, *hB, *o4, *cols, *dcn;
    cudaGetSymbolAddress((void**)&fb,  g_fb);
    cudaGetSymbolAddress((void**)&ff,  g_ff);
    cudaGetSymbolAddress((void**)&hA,  g_hA);
    cudaGetSymbolAddress((void**)&hB,  g_hB);
    cudaGetSymbolAddress((void**)&o4,  g_out4);
    cudaGetSymbolAddress((void**)&cols, g_cols);
    cudaGetSymbolAddress((void**)&dcn, g_dcn);

    const dim3 gc64(18, 16);
    const dim3 gc432(18, 108);
    const dim3 gg64(36, 8);

    for (int br = 0; br < 2; br++) {
        const float* const* p = P[br];
        float* F = (br == 0) ? fb : ff;
        const float* prop = nullptr;

        for (int i = 0; i < 8; i++) {
            const int fr = (br == 0) ? (7 - i) : i;
            const float* cur = x + fr * CH;
            const float* n2 = nullptr;
            if (i > 1) {
                int fr2 = (br == 0) ? (7 - (i - 2)) : (i - 2);
                n2 = F + fr2 * CH;
            }

            if (i > 0) {
                conv3x3_k<<<gc64, 128, CONV_SMEM>>>(prop, cur, n2, 3, p[2], p[3], nullptr, hA, 1);
                conv3x3_k<<<gc64, 128, CONV_SMEM>>>(hA, nullptr, nullptr, 1, p[4], p[5], nullptr, hB, 1);
                conv3x3_k<<<gc64, 128, CONV_SMEM>>>(hB, nullptr, nullptr, 1, p[6], p[7], nullptr, hA, 1);
                conv3x3_k<<<gc432, 128, CONV_SMEM>>>(hA, nullptr, nullptr, 1, p[8], p[9], nullptr, o4, 0);
                dcn_sample_k<<<dim3(72, 144), 128>>>(prop, n2, o4, cols);
                gemm_k<<<gg64, 128>>>(cols, cols, 1152, 1152, p[0], p[1], nullptr, dcn);
                prop = dcn;
            }

            if (br == 0)
                conv3x3_k<<<gc64, 128, CONV_SMEM>>>(cur, prop, nullptr, 2, p[10], p[11], nullptr, hA, 1);
            else
                conv3x3_k<<<gc64, 128, CONV_SMEM>>>(cur, fb + fr * CH, prop, 3, p[10], p[11], nullptr, hA, 1);
            conv3x3_k<<<gc64, 128, CONV_SMEM>>>(hA, nullptr, nullptr, 1, p[12], p[13], prop, F + fr * CH, 0);
            prop = F + fr * CH;
        }
    }

    for (int f = 0; f < 8; f++) {
        gemm_k<<<gg64, 128>>>(fb + f * CH, ff + f * CH, 64, 128,
                              fus_w, fus_b, x + f * CH, out + f * CH);
    }
}